// round 6
// baseline (speedup 1.0000x reference)
#include <cuda_runtime.h>
#include <cuda_bf16.h>
#include <cstdint>

// Problem constants
#define B_    2
#define L_    512
#define V_    32000
#define TWOV  64000
#define MAXM  4096
#define NT2   500            // 64000/128 vocab tiles

// ---------------- GEMM1 (mma.sync) tiling ----------------
#define BM 128
#define BN 128
#define BK 32
#define SA 40
#define SB 136
#define STAGES 4
#define A_ST (BM * SA * 2)
#define B_ST (BK * SB * 2)
#define G1_SMEM (STAGES * (A_ST + B_ST))

// ---------------- GEMM2: 256x128 CTA tile, 8 warps of 64x64, B-persistent ----------------
#define BM2 256
#define A2_ST (BM2 * SA * 2)               // 20480 B per A stage (BK=32)
#define B2_BYTES (512 * SB * 2)            // 139264 (512K x 128N slice)
#define G2_SCR (B2_BYTES + 4 * A2_ST)      // 221184
#define G2_SMEM (G2_SCR + 5120)            // 226304  (<= 232448)

// ---------------- device scratch ----------------
static __device__ __align__(256) __nv_bfloat16 g_fbB[MAXM * 1024];
static __device__ __align__(256) __nv_bfloat16 g_w1B[1024 * 512];
static __device__ __align__(256) __nv_bfloat16 g_w2B[512 * TWOV];
static __device__ __align__(256) float         g_h32[MAXM * 512];
static __device__ __align__(256) __nv_bfloat16 g_hB [MAXM * 512];
static __device__ __align__(256) float         g_pm [MAXM * NT2];
static __device__ __align__(256) float         g_ps [MAXM * NT2];
static __device__ __align__(256) float         g_nll[MAXM * 2];

// ---------------- PTX helpers ----------------
__device__ __forceinline__ void cpa16(unsigned s, const void* g) {
    asm volatile("cp.async.cg.shared.global [%0], [%1], 16;\n" :: "r"(s), "l"(g));
}
__device__ __forceinline__ void cp_commit() { asm volatile("cp.async.commit_group;\n"); }
template<int N> __device__ __forceinline__ void cp_wait() {
    asm volatile("cp.async.wait_group %0;\n" :: "n"(N));
}
__device__ __forceinline__ void ldsmx4(unsigned* r, unsigned a) {
    asm volatile("ldmatrix.sync.aligned.m8n8.x4.shared.b16 {%0,%1,%2,%3}, [%4];\n"
                 : "=r"(r[0]), "=r"(r[1]), "=r"(r[2]), "=r"(r[3]) : "r"(a));
}
__device__ __forceinline__ void ldsmx4t(unsigned* r, unsigned a) {
    asm volatile("ldmatrix.sync.aligned.m8n8.x4.trans.shared.b16 {%0,%1,%2,%3}, [%4];\n"
                 : "=r"(r[0]), "=r"(r[1]), "=r"(r[2]), "=r"(r[3]) : "r"(a));
}
__device__ __forceinline__ void mma16816(float* c, const unsigned* a, const unsigned* b) {
    asm volatile(
        "mma.sync.aligned.m16n8k16.row.col.f32.bf16.bf16.f32 "
        "{%0,%1,%2,%3}, {%4,%5,%6,%7}, {%8,%9}, {%0,%1,%2,%3};\n"
        : "+f"(c[0]), "+f"(c[1]), "+f"(c[2]), "+f"(c[3])
        : "r"(a[0]), "r"(a[1]), "r"(a[2]), "r"(a[3]), "r"(b[0]), "r"(b[1]));
}

// ---------------- fp32 -> bf16 weight conversion ----------------
__global__ void k_f2bf(const float* __restrict__ src, int which, int n4) {
    __nv_bfloat16* dst = which ? g_w2B : g_w1B;
    int i = blockIdx.x * blockDim.x + threadIdx.x;
    int stride = gridDim.x * blockDim.x;
    for (; i < n4; i += stride) {
        float4 v = reinterpret_cast<const float4*>(src)[i];
        reinterpret_cast<__nv_bfloat162*>(dst)[2 * i]     = __floats2bfloat162_rn(v.x, v.y);
        reinterpret_cast<__nv_bfloat162*>(dst)[2 * i + 1] = __floats2bfloat162_rn(v.z, v.w);
    }
}

// ---------------- gather fb rows -> bf16, zero-pad ----------------
__global__ void k_gather(const float* __restrict__ fwd, const float* __restrict__ bwd,
                         const int* __restrict__ fi, const int* __restrict__ bi,
                         int Np, int M) {
    int row = blockIdx.x;
    if (row < M) {
        int b = row / Np;
        int n = row - b * Np;
        const float* fsrc = fwd + ((size_t)b * L_ + fi[n]) * 512;
        const float* bsrc = bwd + ((size_t)b * L_ + bi[n]) * 512;
        for (int c = threadIdx.x; c < 1024; c += blockDim.x) {
            float v = (c < 512) ? fsrc[c] : bsrc[c - 512];
            g_fbB[(size_t)row * 1024 + c] = __float2bfloat16(v);
        }
    } else {
        for (int c = threadIdx.x; c < 1024; c += blockDim.x)
            g_fbB[(size_t)row * 1024 + c] = __float2bfloat16(0.f);
    }
}

// ---------------- GEMM1: h = leaky_relu(fb @ w1 + b1)  (mma.sync, 256 thr) ----------------
__global__ __launch_bounds__(256) void k_gemm1(const float* __restrict__ b1) {
    extern __shared__ char smem[];
    unsigned sb = (unsigned)__cvta_generic_to_shared(smem);
    const unsigned A0 = sb;
    const unsigned B0 = sb + STAGES * A_ST;
    const int tid = threadIdx.x, lane = tid & 31, wid = tid >> 5;
    const int wm = wid >> 2, wn = wid & 3;
    const int row0 = blockIdx.y * BM, col0 = blockIdx.x * BN;

    const unsigned aoff = ((wm * 64 + (lane & 15)) * SA + (lane >> 4) * 8) * 2;
    const unsigned boff = ((lane & 15) * SB + wn * 32 + (lane >> 4) * 8) * 2;

    float acc[4][4][4];
#pragma unroll
    for (int a = 0; a < 4; a++)
#pragma unroll
        for (int b = 0; b < 4; b++)
#pragma unroll
            for (int c = 0; c < 4; c++) acc[a][b][c] = 0.f;

    auto loadAB = [&](int st, int kk) {
#pragma unroll
        for (int i = 0; i < 2; i++) {
            int r = i * 64 + (tid >> 2), c = (tid & 3) * 8;
            cpa16(A0 + st * A_ST + (unsigned)(r * SA + c) * 2,
                  g_fbB + (size_t)(row0 + r) * 1024 + kk * BK + c);
        }
#pragma unroll
        for (int i = 0; i < 2; i++) {
            int r = i * 16 + (tid >> 4), c = (tid & 15) * 8;
            cpa16(B0 + st * B_ST + (unsigned)(r * SB + c) * 2,
                  g_w1B + (size_t)(kk * BK + r) * 512 + col0 + c);
        }
    };

    const int KT = 1024 / BK;
#pragma unroll
    for (int s = 0; s < STAGES - 1; s++) { loadAB(s, s); cp_commit(); }

    for (int kt = 0; kt < KT; kt++) {
        cp_wait<STAGES - 2>();
        __syncthreads();
        int kl = kt + STAGES - 1;
        if (kl < KT) loadAB(kl & (STAGES - 1), kl);
        cp_commit();
        int st = kt & (STAGES - 1);
        unsigned aS = A0 + st * A_ST + aoff;
        unsigned bS = B0 + st * B_ST + boff;
#pragma unroll
        for (int ks = 0; ks < 2; ks++) {
            unsigned afr[4][4], bfr[2][4];
#pragma unroll
            for (int mf = 0; mf < 4; mf++) ldsmx4(afr[mf], aS + mf * (16 * SA * 2) + ks * 32);
#pragma unroll
            for (int p = 0; p < 2; p++) ldsmx4t(bfr[p], bS + ks * (16 * SB * 2) + p * 32);
#pragma unroll
            for (int mf = 0; mf < 4; mf++) {
                mma16816(acc[mf][0], afr[mf], &bfr[0][0]);
                mma16816(acc[mf][1], afr[mf], &bfr[0][2]);
                mma16816(acc[mf][2], afr[mf], &bfr[1][0]);
                mma16816(acc[mf][3], afr[mf], &bfr[1][2]);
            }
        }
    }

    const int g = lane >> 2, q = lane & 3;
#pragma unroll
    for (int mf = 0; mf < 4; mf++) {
#pragma unroll
        for (int nf = 0; nf < 4; nf++) {
            int cl = col0 + wn * 32 + nf * 8 + q * 2;
#pragma unroll
            for (int i = 0; i < 4; i++) {
                int rr = row0 + wm * 64 + mf * 16 + g + ((i >= 2) ? 8 : 0);
                int cc = cl + (i & 1);
                float v = acc[mf][nf][i] + b1[cc];
                v = v > 0.f ? v : 0.01f * v;
                g_h32[(size_t)rr * 512 + cc] = v;
                g_hB [(size_t)rr * 512 + cc] = __float2bfloat16(v);
            }
        }
    }
}

// ---------------- GEMM2: 256 thr / 8 warps (2x2 grid, 64x64 per warp), B-persistent ----------------
__global__ __launch_bounds__(256, 1) void k_gemm2(const float* __restrict__ b2, int MT) {
    extern __shared__ char smem[];
    unsigned sb = (unsigned)__cvta_generic_to_shared(smem);
    const unsigned Bb = sb;
    const unsigned Ab = sb + B2_BYTES;
    float* red_m  = (float*)(smem + G2_SCR);   // [2][256]
    float* red_s  = red_m + 512;               // [2][256]
    float* rowmax = red_s + 512;               // [256]

    const int tid = threadIdx.x, lane = tid & 31, wid = tid >> 5;
    const int wm = wid >> 1, wn = wid & 1;      // 4x2 warp grid, 64x64 per warp
    const int g = lane >> 2, q = lane & 3;
    const int ct = blockIdx.x;
    const int col0 = ct * 128;

    // Load persistent B slice: 512 K-rows x 128 N-cols bf16 (group 0)
    for (int i = tid; i < 8192; i += 256) {
        int r = i >> 4, c = (i & 15) * 8;
        cpa16(Bb + (unsigned)(r * SB + c) * 2, g_w2B + (size_t)r * TWOV + col0 + c);
    }
    cp_commit();

    const unsigned aoff = ((wm * 64 + (lane & 15)) * SA + (lane >> 4) * 8) * 2;
    const unsigned boff = ((lane & 15) * SB + wn * 64 + (lane >> 4) * 8) * 2;

    float bv[8][2];
#pragma unroll
    for (int nf = 0; nf < 8; nf++) {
        int cc = col0 + wn * 64 + nf * 8 + q * 2;
        bv[nf][0] = b2[cc];
        bv[nf][1] = b2[cc + 1];
    }

    // A-stage loader: chunk c = rb*16 + kt (256 rows x 32 K-cols)
    auto loadA = [&](int st, int cidx) {
        int rb = cidx >> 4, kt = cidx & 15;
        const __nv_bfloat16* base = g_hB + (size_t)(rb * BM2) * 512 + kt * 32;
#pragma unroll
        for (int i = 0; i < 4; i++) {
            int idx = tid + i * 256;
            int r = idx >> 2, c = (idx & 3) * 8;
            cpa16(Ab + st * A2_ST + (unsigned)(r * SA + c) * 2, base + (size_t)r * 512 + c);
        }
    };

    const int T = MT * 16;
#pragma unroll
    for (int s = 0; s < 3; s++) { loadA(s, s); cp_commit(); }

    int c = 0;
    for (int rb = 0; rb < MT; rb++) {
        float acc[4][8][4];
#pragma unroll
        for (int a = 0; a < 4; a++)
#pragma unroll
            for (int b = 0; b < 8; b++)
#pragma unroll
                for (int e = 0; e < 4; e++) acc[a][b][e] = 0.f;

        for (int kt = 0; kt < 16; kt++, c++) {
            cp_wait<2>();
            __syncthreads();
            int cl = c + 3;
            if (cl < T) loadA(cl & 3, cl);
            cp_commit();
            unsigned aS = Ab + (c & 3) * A2_ST + aoff;
            unsigned bS = Bb + (unsigned)(kt * 32 * SB) * 2 + boff;
#pragma unroll
            for (int ks = 0; ks < 2; ks++) {
                unsigned afr[4][4], bfr[4][4];
#pragma unroll
                for (int mf = 0; mf < 4; mf++)
                    ldsmx4(afr[mf], aS + mf * (16 * SA * 2) + ks * 32);
#pragma unroll
                for (int p = 0; p < 4; p++)
                    ldsmx4t(bfr[p], bS + ks * (16 * SB * 2) + p * 32);
#pragma unroll
                for (int mf = 0; mf < 4; mf++) {
#pragma unroll
                    for (int p = 0; p < 4; p++) {
                        mma16816(acc[mf][p * 2],     afr[mf], &bfr[p][0]);
                        mma16816(acc[mf][p * 2 + 1], afr[mf], &bfr[p][2]);
                    }
                }
            }
        }

        // ---- epilogue: per-row tile max + sumexp partials (next block's A in flight) ----
        __syncthreads();
#pragma unroll
        for (int mf = 0; mf < 4; mf++) {
#pragma unroll
            for (int rh = 0; rh < 2; rh++) {
                float m = -1e30f;
#pragma unroll
                for (int nf = 0; nf < 8; nf++) {
                    m = fmaxf(m, acc[mf][nf][rh * 2 + 0] + bv[nf][0]);
                    m = fmaxf(m, acc[mf][nf][rh * 2 + 1] + bv[nf][1]);
                }
                m = fmaxf(m, __shfl_xor_sync(0xffffffffu, m, 1));
                m = fmaxf(m, __shfl_xor_sync(0xffffffffu, m, 2));
                if (q == 0) red_m[wn * 256 + wm * 64 + mf * 16 + rh * 8 + g] = m;
            }
        }
        __syncthreads();
        if (tid < 256) rowmax[tid] = fmaxf(red_m[tid], red_m[256 + tid]);
        __syncthreads();
#pragma unroll
        for (int mf = 0; mf < 4; mf++) {
#pragma unroll
            for (int rh = 0; rh < 2; rh++) {
                int rl = wm * 64 + mf * 16 + rh * 8 + g;
                float rm = rowmax[rl];
                float s = 0.f;
#pragma unroll
                for (int nf = 0; nf < 8; nf++) {
                    s += __expf(acc[mf][nf][rh * 2 + 0] + bv[nf][0] - rm);
                    s += __expf(acc[mf][nf][rh * 2 + 1] + bv[nf][1] - rm);
                }
                s += __shfl_xor_sync(0xffffffffu, s, 1);
                s += __shfl_xor_sync(0xffffffffu, s, 2);
                if (q == 0) red_s[wn * 256 + rl] = s;
            }
        }
        __syncthreads();
        if (tid < 256) {
            float s = red_s[tid] + red_s[256 + tid];
            int rowg = rb * BM2 + tid;
            g_pm[(size_t)rowg * NT2 + ct] = rowmax[tid];
            g_ps[(size_t)rowg * NT2 + ct] = s;
        }
        __syncthreads();
    }
}

// ---------------- per-(row,branch) lse merge + label logit + nll ----------------
__global__ void k_reduce(const int* __restrict__ seq, const int* __restrict__ fi,
                         const int* __restrict__ bi, const float* __restrict__ w2,
                         const float* __restrict__ b2, int Np, int M) {
    int gw = (blockIdx.x * blockDim.x + threadIdx.x) >> 5;
    int lane = threadIdx.x & 31;
    if (gw >= M * 2) return;
    int r = gw >> 1, br = gw & 1;
    int b = r / Np, n = r - b * Np;
    int pos = br ? bi[n] : fi[n];
    int label = seq[b * L_ + pos];
    int col = br * V_ + label;

    const float* pm = g_pm + (size_t)r * NT2 + br * 250;
    const float* ps = g_ps + (size_t)r * NT2 + br * 250;
    float m = -1e30f;
    for (int i = lane; i < 250; i += 32) m = fmaxf(m, pm[i]);
#pragma unroll
    for (int o = 16; o; o >>= 1) m = fmaxf(m, __shfl_xor_sync(0xffffffffu, m, o));
    float s = 0.f;
    for (int i = lane; i < 250; i += 32) s += ps[i] * __expf(pm[i] - m);
#pragma unroll
    for (int o = 16; o; o >>= 1) s += __shfl_xor_sync(0xffffffffu, s, o);
    float lse = m + logf(s);

    float dot = 0.f;
    for (int k = lane; k < 512; k += 32)
        dot += g_h32[(size_t)r * 512 + k] * w2[(size_t)k * TWOV + col];
#pragma unroll
    for (int o = 16; o; o >>= 1) dot += __shfl_xor_sync(0xffffffffu, dot, o);

    if (lane == 0) {
        float nll = lse - (dot + b2[col]);
        g_nll[gw] = nll * (br ? 0.25f : 1.0f);
    }
}

// ---------------- deterministic final mean ----------------
__global__ void k_final(float* __restrict__ out, int M) {
    __shared__ float sh[256];
    float s = 0.f;
    for (int i = threadIdx.x; i < 2 * M; i += 256) s += g_nll[i];
    sh[threadIdx.x] = s;
    __syncthreads();
    for (int o = 128; o; o >>= 1) {
        if (threadIdx.x < o) sh[threadIdx.x] += sh[threadIdx.x + o];
        __syncthreads();
    }
    if (threadIdx.x == 0) out[0] = sh[0] / (float)(2 * M);
}

// ---------------- launch ----------------
extern "C" void kernel_launch(void* const* d_in, const int* in_sizes, int n_in,
                              void* d_out, int out_size) {
    const float* fwd = (const float*)d_in[0];
    const float* bwd = (const float*)d_in[1];
    const int*   seq = (const int*)  d_in[2];
    const int*   fi  = (const int*)  d_in[3];
    const int*   bi  = (const int*)  d_in[4];
    const float* w1  = (const float*)d_in[5];
    const float* b1  = (const float*)d_in[6];
    const float* w2  = (const float*)d_in[7];
    const float* b2  = (const float*)d_in[8];

    int Np = in_sizes[3];
    int M  = B_ * Np;
    int MT2 = (M + BM2 - 1) / BM2;          // 256-row blocks for GEMM2
    int Mpad = MT2 * BM2;                   // pad to 256 multiple

    cudaFuncSetAttribute(k_gemm1, cudaFuncAttributeMaxDynamicSharedMemorySize, G1_SMEM);
    cudaFuncSetAttribute(k_gemm2, cudaFuncAttributeMaxDynamicSharedMemorySize, G2_SMEM);

    k_f2bf<<<256, 256>>>(w1, 0, (1024 * 512) / 4);
    k_f2bf<<<2048, 256>>>(w2, 1, (512 * TWOV) / 4);
    k_gather<<<Mpad, 256>>>(fwd, bwd, fi, bi, Np, M);

    dim3 g1(512 / BN, Mpad / BM);
    k_gemm1<<<g1, 256, G1_SMEM>>>(b1);

    k_gemm2<<<NT2, 256, G2_SMEM>>>(b2, MT2);

    int warps = M * 2;
    int blocks = (warps * 32 + 255) / 256;
    k_reduce<<<blocks, 256>>>(seq, fi, bi, w2, b2, Np, M);
    k_final<<<1, 256>>>((float*)d_out, M);
}

// round 7
// speedup vs baseline: 1.1934x; 1.1934x over previous
#include <cuda_runtime.h>
#include <cuda_bf16.h>
#include <cstdint>

// Problem constants
#define B_    2
#define L_    512
#define V_    32000
#define TWOV  64000
#define MAXM  4096
#define NT2   500            // 64000/128 vocab tiles

// ---------------- GEMM1 (mma.sync) tiling ----------------
#define BM 128
#define BN 128
#define BK 32
#define SA 40
#define SB 136
#define STAGES 4
#define A_ST (BM * SA * 2)
#define B_ST (BK * SB * 2)
#define G1_SMEM (STAGES * (A_ST + B_ST))

// ---------------- GEMM2 (persistent, 512 thr, 16 warps 32x32, BK=64) ----------------
#define SA2 72                          // 64 + 8 pad bf16 (144B stride)
#define A2_ST (128 * SA2 * 2)           // 18432 B per A stage
#define B2_BYTES (512 * SB * 2)         // 139264 (512K x 128N bf16 slice)
#define G2_SCR (B2_BYTES + 4 * A2_ST)   // 212992
#define G2_SMEM (G2_SCR + 4608)         // 217600

// ---------------- device scratch ----------------
static __device__ __align__(256) __nv_bfloat16 g_fbB[MAXM * 1024];
static __device__ __align__(256) __nv_bfloat16 g_w1B[1024 * 512];
static __device__ __align__(256) float         g_h32[MAXM * 512];
static __device__ __align__(256) __nv_bfloat16 g_hB [MAXM * 512];
static __device__ __align__(256) float         g_pm [MAXM * NT2];
static __device__ __align__(256) float         g_ps [MAXM * NT2];
static __device__ __align__(256) float         g_nll[MAXM * 2];

// ---------------- PTX helpers ----------------
__device__ __forceinline__ void cpa16(unsigned s, const void* g) {
    asm volatile("cp.async.cg.shared.global [%0], [%1], 16;\n" :: "r"(s), "l"(g));
}
__device__ __forceinline__ void cp_commit() { asm volatile("cp.async.commit_group;\n"); }
template<int N> __device__ __forceinline__ void cp_wait() {
    asm volatile("cp.async.wait_group %0;\n" :: "n"(N));
}
__device__ __forceinline__ void ldsmx4(unsigned* r, unsigned a) {
    asm volatile("ldmatrix.sync.aligned.m8n8.x4.shared.b16 {%0,%1,%2,%3}, [%4];\n"
                 : "=r"(r[0]), "=r"(r[1]), "=r"(r[2]), "=r"(r[3]) : "r"(a));
}
__device__ __forceinline__ void ldsmx4t(unsigned* r, unsigned a) {
    asm volatile("ldmatrix.sync.aligned.m8n8.x4.trans.shared.b16 {%0,%1,%2,%3}, [%4];\n"
                 : "=r"(r[0]), "=r"(r[1]), "=r"(r[2]), "=r"(r[3]) : "r"(a));
}
__device__ __forceinline__ void mma16816(float* c, const unsigned* a, const unsigned* b) {
    asm volatile(
        "mma.sync.aligned.m16n8k16.row.col.f32.bf16.bf16.f32 "
        "{%0,%1,%2,%3}, {%4,%5,%6,%7}, {%8,%9}, {%0,%1,%2,%3};\n"
        : "+f"(c[0]), "+f"(c[1]), "+f"(c[2]), "+f"(c[3])
        : "r"(a[0]), "r"(a[1]), "r"(a[2]), "r"(a[3]), "r"(b[0]), "r"(b[1]));
}

// ---------------- fp32 -> bf16 (w1 only) ----------------
__global__ void k_f2bf(const float* __restrict__ src, int n4) {
    int i = blockIdx.x * blockDim.x + threadIdx.x;
    int stride = gridDim.x * blockDim.x;
    for (; i < n4; i += stride) {
        float4 v = reinterpret_cast<const float4*>(src)[i];
        reinterpret_cast<__nv_bfloat162*>(g_w1B)[2 * i]     = __floats2bfloat162_rn(v.x, v.y);
        reinterpret_cast<__nv_bfloat162*>(g_w1B)[2 * i + 1] = __floats2bfloat162_rn(v.z, v.w);
    }
}

// ---------------- gather fb rows -> bf16, zero-pad ----------------
__global__ void k_gather(const float* __restrict__ fwd, const float* __restrict__ bwd,
                         const int* __restrict__ fi, const int* __restrict__ bi,
                         int Np, int M) {
    int row = blockIdx.x;
    if (row < M) {
        int b = row / Np;
        int n = row - b * Np;
        const float* fsrc = fwd + ((size_t)b * L_ + fi[n]) * 512;
        const float* bsrc = bwd + ((size_t)b * L_ + bi[n]) * 512;
        for (int c = threadIdx.x; c < 1024; c += blockDim.x) {
            float v = (c < 512) ? fsrc[c] : bsrc[c - 512];
            g_fbB[(size_t)row * 1024 + c] = __float2bfloat16(v);
        }
    } else {
        for (int c = threadIdx.x; c < 1024; c += blockDim.x)
            g_fbB[(size_t)row * 1024 + c] = __float2bfloat16(0.f);
    }
}

// ---------------- GEMM1: h = leaky_relu(fb @ w1 + b1)  (mma.sync, 256 thr) ----------------
__global__ __launch_bounds__(256) void k_gemm1(const float* __restrict__ b1) {
    extern __shared__ char smem[];
    unsigned sb = (unsigned)__cvta_generic_to_shared(smem);
    const unsigned A0 = sb;
    const unsigned B0 = sb + STAGES * A_ST;
    const int tid = threadIdx.x, lane = tid & 31, wid = tid >> 5;
    const int wm = wid >> 2, wn = wid & 3;
    const int row0 = blockIdx.y * BM, col0 = blockIdx.x * BN;

    const unsigned aoff = ((wm * 64 + (lane & 15)) * SA + (lane >> 4) * 8) * 2;
    const unsigned boff = ((lane & 15) * SB + wn * 32 + (lane >> 4) * 8) * 2;

    float acc[4][4][4];
#pragma unroll
    for (int a = 0; a < 4; a++)
#pragma unroll
        for (int b = 0; b < 4; b++)
#pragma unroll
            for (int c = 0; c < 4; c++) acc[a][b][c] = 0.f;

    auto loadAB = [&](int st, int kk) {
#pragma unroll
        for (int i = 0; i < 2; i++) {
            int r = i * 64 + (tid >> 2), c = (tid & 3) * 8;
            cpa16(A0 + st * A_ST + (unsigned)(r * SA + c) * 2,
                  g_fbB + (size_t)(row0 + r) * 1024 + kk * BK + c);
        }
#pragma unroll
        for (int i = 0; i < 2; i++) {
            int r = i * 16 + (tid >> 4), c = (tid & 15) * 8;
            cpa16(B0 + st * B_ST + (unsigned)(r * SB + c) * 2,
                  g_w1B + (size_t)(kk * BK + r) * 512 + col0 + c);
        }
    };

    const int KT = 1024 / BK;
#pragma unroll
    for (int s = 0; s < STAGES - 1; s++) { loadAB(s, s); cp_commit(); }

    for (int kt = 0; kt < KT; kt++) {
        cp_wait<STAGES - 2>();
        __syncthreads();
        int kl = kt + STAGES - 1;
        if (kl < KT) loadAB(kl & (STAGES - 1), kl);
        cp_commit();
        int st = kt & (STAGES - 1);
        unsigned aS = A0 + st * A_ST + aoff;
        unsigned bS = B0 + st * B_ST + boff;
#pragma unroll
        for (int ks = 0; ks < 2; ks++) {
            unsigned afr[4][4], bfr[2][4];
#pragma unroll
            for (int mf = 0; mf < 4; mf++) ldsmx4(afr[mf], aS + mf * (16 * SA * 2) + ks * 32);
#pragma unroll
            for (int p = 0; p < 2; p++) ldsmx4t(bfr[p], bS + ks * (16 * SB * 2) + p * 32);
#pragma unroll
            for (int mf = 0; mf < 4; mf++) {
                mma16816(acc[mf][0], afr[mf], &bfr[0][0]);
                mma16816(acc[mf][1], afr[mf], &bfr[0][2]);
                mma16816(acc[mf][2], afr[mf], &bfr[1][0]);
                mma16816(acc[mf][3], afr[mf], &bfr[1][2]);
            }
        }
    }

    const int g = lane >> 2, q = lane & 3;
#pragma unroll
    for (int mf = 0; mf < 4; mf++) {
#pragma unroll
        for (int nf = 0; nf < 4; nf++) {
            int cl = col0 + wn * 32 + nf * 8 + q * 2;
#pragma unroll
            for (int i = 0; i < 4; i++) {
                int rr = row0 + wm * 64 + mf * 16 + g + ((i >= 2) ? 8 : 0);
                int cc = cl + (i & 1);
                float v = acc[mf][nf][i] + b1[cc];
                v = v > 0.f ? v : 0.01f * v;
                g_h32[(size_t)rr * 512 + cc] = v;
                g_hB [(size_t)rr * 512 + cc] = __float2bfloat16(v);
            }
        }
    }
}

// ---------------- GEMM2: persistent balanced scheduler over (ct, rb) tasks ----------------
// 512 thr / 16 warps (4x4 grid, 32x32 per warp), BK=64, B slice persistent per ct run.
__global__ __launch_bounds__(512, 1) void k_gemm2(const float* __restrict__ w2,
                                                  const float* __restrict__ b2,
                                                  int MT, int NTASK) {
    extern __shared__ char smem[];
    unsigned sb = (unsigned)__cvta_generic_to_shared(smem);
    const unsigned Bb = sb;
    const unsigned Ab = sb + B2_BYTES;
    float* red_m  = (float*)(smem + G2_SCR);   // [4][128]
    float* red_s  = red_m + 512;               // [4][128]
    float* rowmax = red_s + 512;               // [128]

    const int tid = threadIdx.x, lane = tid & 31, wid = tid >> 5;
    const int wm = wid >> 2, wn = wid & 3;      // 4x4 warp grid, 32x32 tiles
    const int g = lane >> 2, q = lane & 3;

    // contiguous task range for this CTA (tasks sharing ct are adjacent)
    const int t0 = (int)(((long long)blockIdx.x * NTASK) / gridDim.x);
    const int t1 = (int)(((long long)(blockIdx.x + 1) * NTASK) / gridDim.x);
    const int ntask = t1 - t0;
    if (ntask <= 0) return;
    const int NC = ntask * 8;                   // total A chunks in this CTA's stream

    const unsigned aoff = ((wm * 32 + (lane & 15)) * SA2 + (lane >> 4) * 8) * 2;
    const unsigned boff = ((lane & 15) * SB + wn * 32 + (lane >> 4) * 8) * 2;

    // A chunk loader by CTA-local chunk index (rb-addressed; ct-independent)
    auto loadA = [&](int st, int cc) {
        int t = t0 + (cc >> 3), kt = cc & 7;
        int rb = t % MT;
        const __nv_bfloat16* base = g_hB + (size_t)(rb * 128) * 512 + kt * 64;
#pragma unroll
        for (int i = 0; i < 2; i++) {
            int idx = tid + i * 512;
            int r = idx >> 3, cc8 = (idx & 7) * 8;
            cpa16(Ab + st * A2_ST + (unsigned)(r * SA2 + cc8) * 2, base + (size_t)r * 512 + cc8);
        }
    };

    float bv[4][2];
    int cur_ct = -1;
    int c = 0;
    bool first = true;

    for (int ti = 0; ti < ntask; ti++) {
        const int t = t0 + ti;
        const int ct = t / MT;
        const int rb = t - ct * MT;
        const int col0 = ct * 128;

        if (ct != cur_ct) {
            cur_ct = ct;
            cp_wait<0>();           // drain in-flight A prefetches (they remain valid in smem)
            __syncthreads();
            // load B slice (512 K-rows x 128 N-cols) from fp32 w2, convert to bf16
            for (int i = tid; i < 512 * 32; i += 512) {
                int r = i >> 5, c4 = i & 31;
                float4 v = *reinterpret_cast<const float4*>(
                    w2 + (size_t)r * TWOV + col0 + c4 * 4);
                __nv_bfloat162 lo = __floats2bfloat162_rn(v.x, v.y);
                __nv_bfloat162 hi = __floats2bfloat162_rn(v.z, v.w);
                unsigned addr = Bb + (unsigned)(r * SB + c4 * 4) * 2;
                asm volatile("st.shared.v2.b32 [%0], {%1, %2};" :: "r"(addr),
                             "r"(*(unsigned*)&lo), "r"(*(unsigned*)&hi));
            }
#pragma unroll
            for (int nf = 0; nf < 4; nf++) {
                int cc2 = col0 + wn * 32 + nf * 8 + q * 2;
                bv[nf][0] = b2[cc2];
                bv[nf][1] = b2[cc2 + 1];
            }
            __syncthreads();        // B visible before ldmatrix
        }

        if (first) {
            first = false;
#pragma unroll
            for (int s = 0; s < 3; s++) { loadA(s, s); cp_commit(); }
        }

        float acc[2][4][4];
#pragma unroll
        for (int a = 0; a < 2; a++)
#pragma unroll
            for (int b = 0; b < 4; b++)
#pragma unroll
                for (int e = 0; e < 4; e++) acc[a][b][e] = 0.f;

        for (int kt = 0; kt < 8; kt++, c++) {
            cp_wait<2>();
            __syncthreads();
            int cl = c + 3;
            if (cl < NC) loadA(cl & 3, cl);
            cp_commit();
            unsigned aS = Ab + (c & 3) * A2_ST + aoff;
            unsigned bS = Bb + (unsigned)(kt * 64 * SB) * 2 + boff;
#pragma unroll
            for (int ks = 0; ks < 4; ks++) {
                unsigned afr[2][4], bfr[2][4];
#pragma unroll
                for (int mf = 0; mf < 2; mf++)
                    ldsmx4(afr[mf], aS + mf * (16 * SA2 * 2) + ks * 32);
#pragma unroll
                for (int p = 0; p < 2; p++)
                    ldsmx4t(bfr[p], bS + ks * (16 * SB * 2) + p * 32);
#pragma unroll
                for (int mf = 0; mf < 2; mf++) {
                    mma16816(acc[mf][0], afr[mf], &bfr[0][0]);
                    mma16816(acc[mf][1], afr[mf], &bfr[0][2]);
                    mma16816(acc[mf][2], afr[mf], &bfr[1][0]);
                    mma16816(acc[mf][3], afr[mf], &bfr[1][2]);
                }
            }
        }

        // ---- epilogue: per-row tile max + sumexp partials (next task's A in flight) ----
        __syncthreads();
#pragma unroll
        for (int mf = 0; mf < 2; mf++) {
#pragma unroll
            for (int rh = 0; rh < 2; rh++) {
                float m = -1e30f;
#pragma unroll
                for (int nf = 0; nf < 4; nf++) {
                    m = fmaxf(m, acc[mf][nf][rh * 2 + 0] + bv[nf][0]);
                    m = fmaxf(m, acc[mf][nf][rh * 2 + 1] + bv[nf][1]);
                }
                m = fmaxf(m, __shfl_xor_sync(0xffffffffu, m, 1));
                m = fmaxf(m, __shfl_xor_sync(0xffffffffu, m, 2));
                if (q == 0) red_m[wn * 128 + wm * 32 + mf * 16 + rh * 8 + g] = m;
            }
        }
        __syncthreads();
        if (tid < 128)
            rowmax[tid] = fmaxf(fmaxf(red_m[tid], red_m[128 + tid]),
                                fmaxf(red_m[256 + tid], red_m[384 + tid]));
        __syncthreads();
#pragma unroll
        for (int mf = 0; mf < 2; mf++) {
#pragma unroll
            for (int rh = 0; rh < 2; rh++) {
                int rl = wm * 32 + mf * 16 + rh * 8 + g;
                float rm = rowmax[rl];
                float s = 0.f;
#pragma unroll
                for (int nf = 0; nf < 4; nf++) {
                    s += __expf(acc[mf][nf][rh * 2 + 0] + bv[nf][0] - rm);
                    s += __expf(acc[mf][nf][rh * 2 + 1] + bv[nf][1] - rm);
                }
                s += __shfl_xor_sync(0xffffffffu, s, 1);
                s += __shfl_xor_sync(0xffffffffu, s, 2);
                if (q == 0) red_s[wn * 128 + rl] = s;
            }
        }
        __syncthreads();
        if (tid < 128) {
            float s = red_s[tid] + red_s[128 + tid] + red_s[256 + tid] + red_s[384 + tid];
            int rowg = rb * 128 + tid;
            g_pm[(size_t)rowg * NT2 + ct] = rowmax[tid];
            g_ps[(size_t)rowg * NT2 + ct] = s;
        }
        __syncthreads();
    }
}

// ---------------- per-(row,branch) lse merge + label logit + nll ----------------
__global__ void k_reduce(const int* __restrict__ seq, const int* __restrict__ fi,
                         const int* __restrict__ bi, const float* __restrict__ w2,
                         const float* __restrict__ b2, int Np, int M) {
    int gw = (blockIdx.x * blockDim.x + threadIdx.x) >> 5;
    int lane = threadIdx.x & 31;
    if (gw >= M * 2) return;
    int r = gw >> 1, br = gw & 1;
    int b = r / Np, n = r - b * Np;
    int pos = br ? bi[n] : fi[n];
    int label = seq[b * L_ + pos];
    int col = br * V_ + label;

    const float* pm = g_pm + (size_t)r * NT2 + br * 250;
    const float* ps = g_ps + (size_t)r * NT2 + br * 250;
    float m = -1e30f;
    for (int i = lane; i < 250; i += 32) m = fmaxf(m, pm[i]);
#pragma unroll
    for (int o = 16; o; o >>= 1) m = fmaxf(m, __shfl_xor_sync(0xffffffffu, m, o));
    float s = 0.f;
    for (int i = lane; i < 250; i += 32) s += ps[i] * __expf(pm[i] - m);
#pragma unroll
    for (int o = 16; o; o >>= 1) s += __shfl_xor_sync(0xffffffffu, s, o);
    float lse = m + logf(s);

    float dot = 0.f;
    for (int k = lane; k < 512; k += 32)
        dot += g_h32[(size_t)r * 512 + k] * w2[(size_t)k * TWOV + col];
#pragma unroll
    for (int o = 16; o; o >>= 1) dot += __shfl_xor_sync(0xffffffffu, dot, o);

    if (lane == 0) {
        float nll = lse - (dot + b2[col]);
        g_nll[gw] = nll * (br ? 0.25f : 1.0f);
    }
}

// ---------------- deterministic final mean ----------------
__global__ void k_final(float* __restrict__ out, int M) {
    __shared__ float sh[256];
    float s = 0.f;
    for (int i = threadIdx.x; i < 2 * M; i += 256) s += g_nll[i];
    sh[threadIdx.x] = s;
    __syncthreads();
    for (int o = 128; o; o >>= 1) {
        if (threadIdx.x < o) sh[threadIdx.x] += sh[threadIdx.x + o];
        __syncthreads();
    }
    if (threadIdx.x == 0) out[0] = sh[0] / (float)(2 * M);
}

// ---------------- launch ----------------
extern "C" void kernel_launch(void* const* d_in, const int* in_sizes, int n_in,
                              void* d_out, int out_size) {
    const float* fwd = (const float*)d_in[0];
    const float* bwd = (const float*)d_in[1];
    const int*   seq = (const int*)  d_in[2];
    const int*   fi  = (const int*)  d_in[3];
    const int*   bi  = (const int*)  d_in[4];
    const float* w1  = (const float*)d_in[5];
    const float* b1  = (const float*)d_in[6];
    const float* w2  = (const float*)d_in[7];
    const float* b2  = (const float*)d_in[8];

    int Np = in_sizes[3];
    int M  = B_ * Np;
    int MT = (M + BM - 1) / BM;       // 128-row blocks
    int Mpad = MT * BM;

    int nsm = 148;
    cudaDeviceGetAttribute(&nsm, cudaDevAttrMultiProcessorCount, 0);
    int NTASK = NT2 * MT;
    int grid2 = nsm < NTASK ? nsm : NTASK;

    cudaFuncSetAttribute(k_gemm1, cudaFuncAttributeMaxDynamicSharedMemorySize, G1_SMEM);
    cudaFuncSetAttribute(k_gemm2, cudaFuncAttributeMaxDynamicSharedMemorySize, G2_SMEM);

    k_f2bf<<<256, 256>>>(w1, (1024 * 512) / 4);
    k_gather<<<Mpad, 256>>>(fwd, bwd, fi, bi, Np, M);

    dim3 g1(512 / BN, MT);
    k_gemm1<<<g1, 256, G1_SMEM>>>(b1);

    k_gemm2<<<grid2, 512, G2_SMEM>>>(w2, b2, MT, NTASK);

    int warps = M * 2;
    int blocks = (warps * 32 + 255) / 256;
    k_reduce<<<blocks, 256>>>(seq, fi, bi, w2, b2, Np, M);
    k_final<<<1, 256>>>((float*)d_out, M);
}